// round 5
// baseline (speedup 1.0000x reference)
#include <cuda_runtime.h>
#include <cstdint>
#include <cstddef>
#include <cmath>

#define HDIM    1024
#define GDIM    4096
#define BATCH   64
#define TSTEPS  256
#define NLAYERS 4
#define SWP     1028   // padded W row stride (conflict-free)
#define KC      128    // recurrence k-chunk
#define NCH     (HDIM / KC)

// ---------------- scratch (static __device__ — allocation-free) ----------------
__device__ __align__(256) float g_xp[(size_t)TSTEPS * BATCH * GDIM];   // xp of current layer [T][B][4H]
__device__ __align__(256) float g_hs[(size_t)TSTEPS * BATCH * HDIM];   // h chain / layer output [T][B][H]
__device__ __align__(256) float g_zero_h[BATCH * HDIM];                // stays zero (h_{-1})
__device__ int g_ctr;                                                   // grid barrier counter

// ---------------- helpers ----------------
__device__ __forceinline__ uint32_t f2tf(float f) {
    uint32_t r;
    asm("cvt.rna.tf32.f32 %0, %1;" : "=r"(r) : "f"(f));
    return r;
}

__device__ __forceinline__ void mma_tf32(float c[4],
    uint32_t a0, uint32_t a1, uint32_t a2, uint32_t a3,
    uint32_t b0, uint32_t b1)
{
    asm volatile(
        "mma.sync.aligned.m16n8k8.row.col.f32.tf32.tf32.f32 "
        "{%0,%1,%2,%3}, {%4,%5,%6,%7}, {%8,%9}, {%0,%1,%2,%3};\n"
        : "+f"(c[0]), "+f"(c[1]), "+f"(c[2]), "+f"(c[3])
        : "r"(a0), "r"(a1), "r"(a2), "r"(a3), "r"(b0), "r"(b1));
}

__device__ __forceinline__ uint32_t smem_u32(const void* p) {
    return (uint32_t)__cvta_generic_to_shared(p);
}
__device__ __forceinline__ void cp16(uint32_t dst, const void* src) {
    asm volatile("cp.async.cg.shared.global [%0], [%1], 16;\n" :: "r"(dst), "l"(src));
}
#define CP_COMMIT() asm volatile("cp.async.commit_group;\n" ::: "memory")
#define CP_WAIT0()  asm volatile("cp.async.wait_group 0;\n" ::: "memory")
#define CP_WAIT1()  asm volatile("cp.async.wait_group 1;\n" ::: "memory")

// ---------------------------------------------------------------------------
__global__ void reset_kernel() { g_ctr = 0; }

// ---------------------------------------------------------------------------
// Layer-0 input projection (exact fp32, 2 MACs/output)
// ---------------------------------------------------------------------------
__global__ void layer0_xp_kernel(const float* __restrict__ x, const float* __restrict__ w0,
                                 const float* __restrict__ bih, const float* __restrict__ bhh)
{
    const int idx = blockIdx.x * 256 + threadIdx.x;
    const int g = idx & (GDIM - 1);
    const int m = idx >> 12;           // t*64 + b
    const int t = m >> 6;
    const int b = m & 63;
    const float x0 = x[(b * TSTEPS + t) * 2 + 0];
    const float x1 = x[(b * TSTEPS + t) * 2 + 1];
    g_xp[idx] = x0 * w0[2 * g] + x1 * w0[2 * g + 1] + bih[g] + bhh[g];
}

// ---------------------------------------------------------------------------
// Input projection layers 1..3: g_xp = g_hs @ w_ih^T + (b_ih+b_hh)
// CTA tile 128x64, 8 warps each 32x32, chunk k=32 double-buffered cp.async.
// grid = (64 n-blocks, 128 m-blocks), 256 threads.
// ---------------------------------------------------------------------------
__global__ __launch_bounds__(256) void proj_kernel(
    const float* __restrict__ wih,
    const float* __restrict__ bih,
    const float* __restrict__ bhh)
{
    extern __shared__ uint32_t psh[];
    uint32_t* sA = psh;                 // 2 * 128*36
    uint32_t* sB = psh + 2 * 128 * 36;  // 2 * 64*36

    const int nb = blockIdx.x;   // 0..63
    const int mb = blockIdx.y;   // 0..127
    const float* A  = g_hs + (size_t)mb * 128 * HDIM;
    const float* Bm = wih  + (size_t)nb * 64 * HDIM;

    const int tid  = threadIdx.x, lane = tid & 31, wp = tid >> 5;
    const int mrow = (wp >> 1) * 32;
    const int nbase = (wp & 1) * 32;
    const int gid = lane >> 2, tig = lane & 3;

    const int arow = tid >> 1, acol = (tid & 1) * 16;  // A: 128 rows, 16 floats/thread
    const int brow = tid >> 2, bcol = (tid & 3) * 8;   // B: 64 rows, 8 floats/thread
    const uint32_t sAa = smem_u32(sA), sBa = smem_u32(sB);

    auto issue = [&](int ch) {
        const int kc = ch * 32, bi = ch & 1;
        const float* as = A + (size_t)arow * HDIM + kc + acol;
        uint32_t ad = sAa + (uint32_t)(bi * 128 * 36 + arow * 36 + acol) * 4;
        #pragma unroll
        for (int i = 0; i < 4; i++) cp16(ad + i * 16, as + i * 4);
        const float* bs = Bm + (size_t)brow * HDIM + kc + bcol;
        uint32_t bd = sBa + (uint32_t)(bi * 64 * 36 + brow * 36 + bcol) * 4;
        #pragma unroll
        for (int i = 0; i < 2; i++) cp16(bd + i * 16, bs + i * 4);
        CP_COMMIT();
    };

    issue(0); issue(1);
    float acc[2][4][4] = {};

    for (int ch = 0; ch < 32; ch++) {
        if (ch >= 30) { CP_WAIT0(); } else { CP_WAIT1(); }
        __syncthreads();
        const uint32_t* bufA = sA + (ch & 1) * 128 * 36;
        const uint32_t* bufB = sB + (ch & 1) * 64 * 36;
        #pragma unroll
        for (int ki = 0; ki < 4; ki++) {
            const int k0 = ki * 8 + tig;
            uint32_t a[2][4];
            #pragma unroll
            for (int mh = 0; mh < 2; mh++) {
                const int rr = mrow + mh * 16 + gid;
                a[mh][0] = bufA[rr * 36 + k0];
                a[mh][1] = bufA[(rr + 8) * 36 + k0];
                a[mh][2] = bufA[rr * 36 + k0 + 4];
                a[mh][3] = bufA[(rr + 8) * 36 + k0 + 4];
            }
            #pragma unroll
            for (int nt = 0; nt < 4; nt++) {
                const int nbr = nbase + nt * 8 + gid;
                uint32_t b0 = bufB[nbr * 36 + k0];
                uint32_t b1 = bufB[nbr * 36 + k0 + 4];
                mma_tf32(acc[0][nt], a[0][0], a[0][1], a[0][2], a[0][3], b0, b1);
                mma_tf32(acc[1][nt], a[1][0], a[1][1], a[1][2], a[1][3], b0, b1);
            }
        }
        __syncthreads();
        if (ch + 2 < 32) issue(ch + 2);
    }

    #pragma unroll
    for (int mh = 0; mh < 2; mh++) {
        #pragma unroll
        for (int nt = 0; nt < 4; nt++) {
            const int c = nbase + nt * 8 + tig * 2;
            const int n = nb * 64 + c;
            const float b0v = bih[n] + bhh[n];
            const float b1v = bih[n + 1] + bhh[n + 1];
            const int r0 = mrow + mh * 16 + gid, r1 = r0 + 8;
            float* o0 = g_xp + ((size_t)mb * 128 + r0) * GDIM + n;
            float* o1 = g_xp + ((size_t)mb * 128 + r1) * GDIM + n;
            o0[0] = acc[mh][nt][0] + b0v;
            o0[1] = acc[mh][nt][1] + b1v;
            o1[0] = acc[mh][nt][2] + b0v;
            o1[1] = acc[mh][nt][3] + b1v;
        }
    }
}

// ---------------------------------------------------------------------------
// Persistent LSTM layer kernel: 128 CTAs x 256 threads, all 256 timesteps.
// CTA u owns hidden units [u*8,u*8+8) x all 4 gate types (32 W_hh rows in SMEM,
// tf32 RNA-converted once). h chunks (k=128) double-buffered via cp.async; h is
// stored RNA-rounded tf32 so raw-bit MMA consumption is exact-tf32.
// ---------------------------------------------------------------------------
__global__ __launch_bounds__(256, 1) void lstm_layer_kernel(
    const float* __restrict__ whh, int step_base /* layer*TSTEPS */)
{
    extern __shared__ uint32_t sh[];
    uint32_t* sW  = sh;                          // 32*SWP
    uint32_t* sA  = sW + 32 * SWP;               // 2 * 64*132
    float*    sXP = (float*)(sA + 2 * 64 * 132); // 64*32
    float*    sG  = sXP + 64 * 32;               // 64*33
    float*    sC  = sG + 64 * 33;                // 512

    const int tid = threadIdx.x;
    const int u   = blockIdx.x;                  // 0..127

    // W_hh rows [i0..7, f0..7, g0..7, o0..7] for this unit block (once/layer)
    for (int idx = tid; idx < 32 * HDIM; idx += 256) {
        const int r = idx >> 10, k = idx & (HDIM - 1);
        const int tau = r >> 3, j = r & 7;
        sW[r * SWP + k] = f2tf(whh[((size_t)(tau * HDIM + u * 8 + j)) * HDIM + k]);
    }
    for (int i = tid; i < 512; i += 256) sC[i] = 0.f;
    __syncthreads();

    const int lane = tid & 31, wp = tid >> 5;
    const int mrow = (wp >> 1) * 16;
    const int ncol = (wp & 1) * 16;
    const int gid  = lane >> 2, tig = lane & 3;

    const int car = tid >> 2;            // copy row 0..63
    const int cac = (tid & 3) * 32;      // copy col base (32 floats/thread)
    const uint32_t sAa  = smem_u32(sA);
    const uint32_t sXPa = smem_u32(sXP);

    for (int t = 0; t < TSTEPS; t++) {
        const float* h_prev = t ? (g_hs + (size_t)(t - 1) * (BATCH * HDIM)) : g_zero_h;
        const float* xp_t   = g_xp + (size_t)t * (BATCH * GDIM);

        // group 0: xp tile (64x32, contiguous 8-float runs) + h chunk 0
        {
            const int s0 = tid, s1 = tid + 256;
            const int r0s = s0 >> 3, w0 = s0 & 7;
            cp16(sXPa + (uint32_t)(r0s * 32 + (w0 >> 1) * 8 + (w0 & 1) * 4) * 4,
                 xp_t + (size_t)r0s * GDIM + (w0 >> 1) * HDIM + u * 8 + (w0 & 1) * 4);
            const int r1s = s1 >> 3, w1 = s1 & 7;
            cp16(sXPa + (uint32_t)(r1s * 32 + (w1 >> 1) * 8 + (w1 & 1) * 4) * 4,
                 xp_t + (size_t)r1s * GDIM + (w1 >> 1) * HDIM + u * 8 + (w1 & 1) * 4);
            const float* src = h_prev + (size_t)car * HDIM + cac;
            uint32_t dst = sAa + (uint32_t)(car * 132 + cac) * 4;
            #pragma unroll
            for (int i = 0; i < 8; i++) cp16(dst + i * 16, src + i * 4);
            CP_COMMIT();
        }
        // group 1: h chunk 1
        {
            const float* src = h_prev + (size_t)car * HDIM + KC + cac;
            uint32_t dst = sAa + (uint32_t)(64 * 132 + car * 132 + cac) * 4;
            #pragma unroll
            for (int i = 0; i < 8; i++) cp16(dst + i * 16, src + i * 4);
            CP_COMMIT();
        }

        float acc[2][4] = {};

        #pragma unroll 1
        for (int ch = 0; ch < NCH; ch++) {
            if (ch >= NCH - 2) { CP_WAIT0(); } else { CP_WAIT1(); }
            __syncthreads();
            const uint32_t* buf = sA + (ch & 1) * 64 * 132;
            const uint32_t* wb  = sW + ch * KC;
            #pragma unroll
            for (int ki = 0; ki < 16; ki++) {
                const int k0 = ki * 8 + tig;
                uint32_t a0 = buf[(mrow + gid)     * 132 + k0];
                uint32_t a1 = buf[(mrow + gid + 8) * 132 + k0];
                uint32_t a2 = buf[(mrow + gid)     * 132 + k0 + 4];
                uint32_t a3 = buf[(mrow + gid + 8) * 132 + k0 + 4];
                #pragma unroll
                for (int nt = 0; nt < 2; nt++) {
                    const int nbr = ncol + nt * 8 + gid;
                    uint32_t b0 = wb[nbr * SWP + k0];
                    uint32_t b1 = wb[nbr * SWP + k0 + 4];
                    mma_tf32(acc[nt], a0, a1, a2, a3, b0, b1);
                }
            }
            __syncthreads();
            if (ch + 2 < NCH) {
                const float* src = h_prev + (size_t)car * HDIM + (ch + 2) * KC + cac;
                uint32_t dst = sAa + (uint32_t)((ch & 1) * 64 * 132 + car * 132 + cac) * 4;
                #pragma unroll
                for (int i = 0; i < 8; i++) cp16(dst + i * 16, src + i * 4);
                CP_COMMIT();
            }
        }

        // gates = acc + xp -> sG
        const int r0 = mrow + gid, r1 = r0 + 8;
        #pragma unroll
        for (int nt = 0; nt < 2; nt++) {
            const int c = ncol + nt * 8 + tig * 2;
            sG[r0 * 33 + c]     = acc[nt][0] + sXP[r0 * 32 + c];
            sG[r0 * 33 + c + 1] = acc[nt][1] + sXP[r0 * 32 + c + 1];
            sG[r1 * 33 + c]     = acc[nt][2] + sXP[r1 * 32 + c];
            sG[r1 * 33 + c + 1] = acc[nt][3] + sXP[r1 * 32 + c + 1];
        }
        __syncthreads();

        // CTA-local elementwise update; h stored RNA-rounded to tf32
        float* hs_out = g_hs + (size_t)t * (BATCH * HDIM);
        #pragma unroll
        for (int e = tid; e < 512; e += 256) {
            const int b = e >> 3, j = e & 7;
            float iv = sG[b * 33 + j];
            float fv = sG[b * 33 + 8 + j];
            float gv = sG[b * 33 + 16 + j];
            float ov = sG[b * 33 + 24 + j];
            iv = 1.f / (1.f + __expf(-iv));
            fv = 1.f / (1.f + __expf(-fv));
            gv = tanhf(gv);
            ov = 1.f / (1.f + __expf(-ov));
            const float cn = fv * sC[e] + iv * gv;
            sC[e] = cn;
            hs_out[b * HDIM + u * 8 + j] = __uint_as_float(f2tf(ov * tanhf(cn)));
        }

        // grid barrier (release h_t, wait for all 128 CTAs)
        __threadfence();
        __syncthreads();
        if (tid == 0) {
            atomicAdd(&g_ctr, 1);
            const int target = 128 * (step_base + t + 1);
            while (*((volatile int*)&g_ctr) < target) __nanosleep(16);
        }
        __syncthreads();
        __threadfence();
    }
}

// ---------------------------------------------------------------------------
__global__ void fc_kernel(const float* __restrict__ fc_w, const float* __restrict__ fc_b,
                          float* __restrict__ out)
{
    const int b = blockIdx.x;
    const float* h = g_hs + (size_t)(TSTEPS - 1) * (BATCH * HDIM) + (size_t)b * HDIM;
    float s = 0.f;
    for (int k = threadIdx.x; k < HDIM; k += 256) s += h[k] * fc_w[k];
    #pragma unroll
    for (int o = 16; o > 0; o >>= 1) s += __shfl_down_sync(0xffffffffu, s, o);
    __shared__ float red[8];
    if ((threadIdx.x & 31) == 0) red[threadIdx.x >> 5] = s;
    __syncthreads();
    if (threadIdx.x == 0) {
        float v = 0.f;
        #pragma unroll
        for (int i = 0; i < 8; i++) v += red[i];
        out[b] = v + fc_b[0];
    }
}

// ---------------------------------------------------------------------------
extern "C" void kernel_launch(void* const* d_in, const int* in_sizes, int n_in,
                              void* d_out, int out_size)
{
    (void)in_sizes; (void)n_in; (void)out_size;
    const float* x      = (const float*)d_in[0];
    const float* w_ih0  = (const float*)d_in[1];
    const float* w_rest = (const float*)d_in[2];
    const float* w_hh   = (const float*)d_in[3];
    const float* b_ih   = (const float*)d_in[4];
    const float* b_hh   = (const float*)d_in[5];
    const float* fc_w   = (const float*)d_in[6];
    const float* fc_b   = (const float*)d_in[7];
    float* out = (float*)d_out;

    const int lstm_smem = (32 * SWP + 2 * 64 * 132) * 4 + (64 * 32 + 64 * 33 + 512) * 4; // 217,856 B
    const int proj_smem = (2 * 128 * 36 + 2 * 64 * 36) * 4;                               // 55,296 B
    static bool attr_set = false;
    if (!attr_set) {
        cudaFuncSetAttribute(lstm_layer_kernel,
                             cudaFuncAttributeMaxDynamicSharedMemorySize, lstm_smem);
        cudaFuncSetAttribute(proj_kernel,
                             cudaFuncAttributeMaxDynamicSharedMemorySize, proj_smem);
        attr_set = true;
    }

    reset_kernel<<<1, 1>>>();

    layer0_xp_kernel<<<(TSTEPS * BATCH * GDIM) / 256, 256>>>(x, w_ih0, b_ih, b_hh);

    for (int l = 0; l < NLAYERS; l++) {
        if (l > 0) {
            proj_kernel<<<dim3(64, 128), 256, proj_smem>>>(
                w_rest + (size_t)(l - 1) * GDIM * HDIM,
                b_ih + (size_t)l * GDIM,
                b_hh + (size_t)l * GDIM);
        }
        lstm_layer_kernel<<<128, 256, lstm_smem>>>(
            w_hh + (size_t)l * GDIM * HDIM, l * TSTEPS);
    }

    fc_kernel<<<BATCH, 256>>>(fc_w, fc_b, out);
}

// round 6
// speedup vs baseline: 1.0051x; 1.0051x over previous
#include <cuda_runtime.h>
#include <cstdint>
#include <cstddef>
#include <cmath>

#define HDIM    1024
#define GDIM    4096
#define BATCH   64
#define TSTEPS  256
#define NLAYERS 4
#define SWP     1028   // padded W row stride (conflict-free)
#define KC      128    // recurrence k-chunk
#define NCH     (HDIM / KC)

// ---------------- scratch (static __device__ — allocation-free) ----------------
__device__ __align__(256) float g_xp[(size_t)TSTEPS * BATCH * GDIM];   // xp of current layer [T][B][4H]
__device__ __align__(256) float g_hs[(size_t)TSTEPS * BATCH * HDIM];   // h chain / layer output [T][B][H]
__device__ __align__(256) float g_zero_h[BATCH * HDIM];                // stays zero (h_{-1})
__device__ int g_ctr;                                                   // grid barrier counter

// ---------------- helpers ----------------
__device__ __forceinline__ uint32_t f2tf(float f) {
    uint32_t r;
    asm("cvt.rna.tf32.f32 %0, %1;" : "=r"(r) : "f"(f));
    return r;
}

__device__ __forceinline__ void mma_tf32(float c[4],
    uint32_t a0, uint32_t a1, uint32_t a2, uint32_t a3,
    uint32_t b0, uint32_t b1)
{
    asm volatile(
        "mma.sync.aligned.m16n8k8.row.col.f32.tf32.tf32.f32 "
        "{%0,%1,%2,%3}, {%4,%5,%6,%7}, {%8,%9}, {%0,%1,%2,%3};\n"
        : "+f"(c[0]), "+f"(c[1]), "+f"(c[2]), "+f"(c[3])
        : "r"(a0), "r"(a1), "r"(a2), "r"(a3), "r"(b0), "r"(b1));
}

__device__ __forceinline__ uint32_t smem_u32(const void* p) {
    return (uint32_t)__cvta_generic_to_shared(p);
}
__device__ __forceinline__ void cp16(uint32_t dst, const void* src) {
    asm volatile("cp.async.cg.shared.global [%0], [%1], 16;\n" :: "r"(dst), "l"(src));
}
#define CP_COMMIT() asm volatile("cp.async.commit_group;\n" ::: "memory")
#define CP_WAIT0()  asm volatile("cp.async.wait_group 0;\n" ::: "memory")
#define CP_WAIT1()  asm volatile("cp.async.wait_group 1;\n" ::: "memory")

// ---------------------------------------------------------------------------
__global__ void reset_kernel() { g_ctr = 0; }

// ---------------------------------------------------------------------------
// Layer-0 input projection (exact fp32, 2 MACs/output)
// ---------------------------------------------------------------------------
__global__ void layer0_xp_kernel(const float* __restrict__ x, const float* __restrict__ w0,
                                 const float* __restrict__ bih, const float* __restrict__ bhh)
{
    const int idx = blockIdx.x * 256 + threadIdx.x;
    const int g = idx & (GDIM - 1);
    const int m = idx >> 12;           // t*64 + b
    const int t = m >> 6;
    const int b = m & 63;
    const float x0 = x[(b * TSTEPS + t) * 2 + 0];
    const float x1 = x[(b * TSTEPS + t) * 2 + 1];
    g_xp[idx] = x0 * w0[2 * g] + x1 * w0[2 * g + 1] + bih[g] + bhh[g];
}

// ---------------------------------------------------------------------------
// Input projection layers 1..3: g_xp = g_hs @ w_ih^T + (b_ih+b_hh)
// CTA tile 128x64, 8 warps each 32x32, chunk k=32 double-buffered cp.async.
// grid = (64 n-blocks, 128 m-blocks), 256 threads.
// ---------------------------------------------------------------------------
__global__ __launch_bounds__(256) void proj_kernel(
    const float* __restrict__ wih,
    const float* __restrict__ bih,
    const float* __restrict__ bhh)
{
    extern __shared__ uint32_t psh[];
    uint32_t* sA = psh;                 // 2 * 128*36
    uint32_t* sB = psh + 2 * 128 * 36;  // 2 * 64*36

    const int nb = blockIdx.x;   // 0..63
    const int mb = blockIdx.y;   // 0..127
    const float* A  = g_hs + (size_t)mb * 128 * HDIM;
    const float* Bm = wih  + (size_t)nb * 64 * HDIM;

    const int tid  = threadIdx.x, lane = tid & 31, wp = tid >> 5;
    const int mrow = (wp >> 1) * 32;
    const int nbase = (wp & 1) * 32;
    const int gid = lane >> 2, tig = lane & 3;

    const int arow = tid >> 1, acol = (tid & 1) * 16;  // A: 128 rows, 16 floats/thread
    const int brow = tid >> 2, bcol = (tid & 3) * 8;   // B: 64 rows, 8 floats/thread
    const uint32_t sAa = smem_u32(sA), sBa = smem_u32(sB);

    auto issue = [&](int ch) {
        const int kc = ch * 32, bi = ch & 1;
        const float* as = A + (size_t)arow * HDIM + kc + acol;
        uint32_t ad = sAa + (uint32_t)(bi * 128 * 36 + arow * 36 + acol) * 4;
        #pragma unroll
        for (int i = 0; i < 4; i++) cp16(ad + i * 16, as + i * 4);
        const float* bs = Bm + (size_t)brow * HDIM + kc + bcol;
        uint32_t bd = sBa + (uint32_t)(bi * 64 * 36 + brow * 36 + bcol) * 4;
        #pragma unroll
        for (int i = 0; i < 2; i++) cp16(bd + i * 16, bs + i * 4);
        CP_COMMIT();
    };

    issue(0); issue(1);
    float acc[2][4][4] = {};

    for (int ch = 0; ch < 32; ch++) {
        if (ch >= 30) { CP_WAIT0(); } else { CP_WAIT1(); }
        __syncthreads();
        const uint32_t* bufA = sA + (ch & 1) * 128 * 36;
        const uint32_t* bufB = sB + (ch & 1) * 64 * 36;
        #pragma unroll
        for (int ki = 0; ki < 4; ki++) {
            const int k0 = ki * 8 + tig;
            uint32_t a[2][4];
            #pragma unroll
            for (int mh = 0; mh < 2; mh++) {
                const int rr = mrow + mh * 16 + gid;
                a[mh][0] = bufA[rr * 36 + k0];
                a[mh][1] = bufA[(rr + 8) * 36 + k0];
                a[mh][2] = bufA[rr * 36 + k0 + 4];
                a[mh][3] = bufA[(rr + 8) * 36 + k0 + 4];
            }
            #pragma unroll
            for (int nt = 0; nt < 4; nt++) {
                const int nbr = nbase + nt * 8 + gid;
                uint32_t b0 = bufB[nbr * 36 + k0];
                uint32_t b1 = bufB[nbr * 36 + k0 + 4];
                mma_tf32(acc[0][nt], a[0][0], a[0][1], a[0][2], a[0][3], b0, b1);
                mma_tf32(acc[1][nt], a[1][0], a[1][1], a[1][2], a[1][3], b0, b1);
            }
        }
        __syncthreads();
        if (ch + 2 < 32) issue(ch + 2);
    }

    #pragma unroll
    for (int mh = 0; mh < 2; mh++) {
        #pragma unroll
        for (int nt = 0; nt < 4; nt++) {
            const int c = nbase + nt * 8 + tig * 2;
            const int n = nb * 64 + c;
            const float b0v = bih[n] + bhh[n];
            const float b1v = bih[n + 1] + bhh[n + 1];
            const int r0 = mrow + mh * 16 + gid, r1 = r0 + 8;
            float* o0 = g_xp + ((size_t)mb * 128 + r0) * GDIM + n;
            float* o1 = g_xp + ((size_t)mb * 128 + r1) * GDIM + n;
            o0[0] = acc[mh][nt][0] + b0v;
            o0[1] = acc[mh][nt][1] + b1v;
            o1[0] = acc[mh][nt][2] + b0v;
            o1[1] = acc[mh][nt][3] + b1v;
        }
    }
}

// ---------------------------------------------------------------------------
// Persistent LSTM layer kernel: 128 CTAs x 256 threads, all 256 timesteps.
// CTA u owns hidden units [u*8,u*8+8) x all 4 gate types (32 W_hh rows in SMEM,
// tf32 RNA-converted once). h chunks (k=128) double-buffered via cp.async; h is
// stored RNA-rounded tf32 so raw-bit MMA consumption is exact-tf32.
// ---------------------------------------------------------------------------
__global__ __launch_bounds__(256, 1) void lstm_layer_kernel(
    const float* __restrict__ whh, int step_base /* layer*TSTEPS */)
{
    extern __shared__ uint32_t sh[];
    uint32_t* sW  = sh;                          // 32*SWP
    uint32_t* sA  = sW + 32 * SWP;               // 2 * 64*132
    float*    sXP = (float*)(sA + 2 * 64 * 132); // 64*32
    float*    sG  = sXP + 64 * 32;               // 64*33
    float*    sC  = sG + 64 * 33;                // 512

    const int tid = threadIdx.x;
    const int u   = blockIdx.x;                  // 0..127

    // W_hh rows [i0..7, f0..7, g0..7, o0..7] for this unit block (once/layer)
    for (int idx = tid; idx < 32 * HDIM; idx += 256) {
        const int r = idx >> 10, k = idx & (HDIM - 1);
        const int tau = r >> 3, j = r & 7;
        sW[r * SWP + k] = f2tf(whh[((size_t)(tau * HDIM + u * 8 + j)) * HDIM + k]);
    }
    for (int i = tid; i < 512; i += 256) sC[i] = 0.f;
    __syncthreads();

    const int lane = tid & 31, wp = tid >> 5;
    const int mrow = (wp >> 1) * 16;
    const int ncol = (wp & 1) * 16;
    const int gid  = lane >> 2, tig = lane & 3;

    const int car = tid >> 2;            // copy row 0..63
    const int cac = (tid & 3) * 32;      // copy col base (32 floats/thread)
    const uint32_t sAa  = smem_u32(sA);
    const uint32_t sXPa = smem_u32(sXP);

    for (int t = 0; t < TSTEPS; t++) {
        const float* h_prev = t ? (g_hs + (size_t)(t - 1) * (BATCH * HDIM)) : g_zero_h;
        const float* xp_t   = g_xp + (size_t)t * (BATCH * GDIM);

        // group 0: xp tile (64x32, contiguous 8-float runs) + h chunk 0
        {
            const int s0 = tid, s1 = tid + 256;
            const int r0s = s0 >> 3, w0 = s0 & 7;
            cp16(sXPa + (uint32_t)(r0s * 32 + (w0 >> 1) * 8 + (w0 & 1) * 4) * 4,
                 xp_t + (size_t)r0s * GDIM + (w0 >> 1) * HDIM + u * 8 + (w0 & 1) * 4);
            const int r1s = s1 >> 3, w1 = s1 & 7;
            cp16(sXPa + (uint32_t)(r1s * 32 + (w1 >> 1) * 8 + (w1 & 1) * 4) * 4,
                 xp_t + (size_t)r1s * GDIM + (w1 >> 1) * HDIM + u * 8 + (w1 & 1) * 4);
            const float* src = h_prev + (size_t)car * HDIM + cac;
            uint32_t dst = sAa + (uint32_t)(car * 132 + cac) * 4;
            #pragma unroll
            for (int i = 0; i < 8; i++) cp16(dst + i * 16, src + i * 4);
            CP_COMMIT();
        }
        // group 1: h chunk 1
        {
            const float* src = h_prev + (size_t)car * HDIM + KC + cac;
            uint32_t dst = sAa + (uint32_t)(64 * 132 + car * 132 + cac) * 4;
            #pragma unroll
            for (int i = 0; i < 8; i++) cp16(dst + i * 16, src + i * 4);
            CP_COMMIT();
        }

        float acc[2][4] = {};

        #pragma unroll 1
        for (int ch = 0; ch < NCH; ch++) {
            if (ch >= NCH - 2) { CP_WAIT0(); } else { CP_WAIT1(); }
            __syncthreads();
            const uint32_t* buf = sA + (ch & 1) * 64 * 132;
            const uint32_t* wb  = sW + ch * KC;
            #pragma unroll
            for (int ki = 0; ki < 16; ki++) {
                const int k0 = ki * 8 + tig;
                uint32_t a0 = buf[(mrow + gid)     * 132 + k0];
                uint32_t a1 = buf[(mrow + gid + 8) * 132 + k0];
                uint32_t a2 = buf[(mrow + gid)     * 132 + k0 + 4];
                uint32_t a3 = buf[(mrow + gid + 8) * 132 + k0 + 4];
                #pragma unroll
                for (int nt = 0; nt < 2; nt++) {
                    const int nbr = ncol + nt * 8 + gid;
                    uint32_t b0 = wb[nbr * SWP + k0];
                    uint32_t b1 = wb[nbr * SWP + k0 + 4];
                    mma_tf32(acc[nt], a0, a1, a2, a3, b0, b1);
                }
            }
            __syncthreads();
            if (ch + 2 < NCH) {
                const float* src = h_prev + (size_t)car * HDIM + (ch + 2) * KC + cac;
                uint32_t dst = sAa + (uint32_t)((ch & 1) * 64 * 132 + car * 132 + cac) * 4;
                #pragma unroll
                for (int i = 0; i < 8; i++) cp16(dst + i * 16, src + i * 4);
                CP_COMMIT();
            }
        }

        // gates = acc + xp -> sG
        const int r0 = mrow + gid, r1 = r0 + 8;
        #pragma unroll
        for (int nt = 0; nt < 2; nt++) {
            const int c = ncol + nt * 8 + tig * 2;
            sG[r0 * 33 + c]     = acc[nt][0] + sXP[r0 * 32 + c];
            sG[r0 * 33 + c + 1] = acc[nt][1] + sXP[r0 * 32 + c + 1];
            sG[r1 * 33 + c]     = acc[nt][2] + sXP[r1 * 32 + c];
            sG[r1 * 33 + c + 1] = acc[nt][3] + sXP[r1 * 32 + c + 1];
        }
        __syncthreads();

        // CTA-local elementwise update; h stored RNA-rounded to tf32
        float* hs_out = g_hs + (size_t)t * (BATCH * HDIM);
        #pragma unroll
        for (int e = tid; e < 512; e += 256) {
            const int b = e >> 3, j = e & 7;
            float iv = sG[b * 33 + j];
            float fv = sG[b * 33 + 8 + j];
            float gv = sG[b * 33 + 16 + j];
            float ov = sG[b * 33 + 24 + j];
            iv = 1.f / (1.f + __expf(-iv));
            fv = 1.f / (1.f + __expf(-fv));
            gv = tanhf(gv);
            ov = 1.f / (1.f + __expf(-ov));
            const float cn = fv * sC[e] + iv * gv;
            sC[e] = cn;
            hs_out[b * HDIM + u * 8 + j] = __uint_as_float(f2tf(ov * tanhf(cn)));
        }

        // grid barrier (release h_t, wait for all 128 CTAs)
        __threadfence();
        __syncthreads();
        if (tid == 0) {
            atomicAdd(&g_ctr, 1);
            const int target = 128 * (step_base + t + 1);
            while (*((volatile int*)&g_ctr) < target) __nanosleep(16);
        }
        __syncthreads();
        __threadfence();
    }
}

// ---------------------------------------------------------------------------
__global__ void fc_kernel(const float* __restrict__ fc_w, const float* __restrict__ fc_b,
                          float* __restrict__ out)
{
    const int b = blockIdx.x;
    const float* h = g_hs + (size_t)(TSTEPS - 1) * (BATCH * HDIM) + (size_t)b * HDIM;
    float s = 0.f;
    for (int k = threadIdx.x; k < HDIM; k += 256) s += h[k] * fc_w[k];
    #pragma unroll
    for (int o = 16; o > 0; o >>= 1) s += __shfl_down_sync(0xffffffffu, s, o);
    __shared__ float red[8];
    if ((threadIdx.x & 31) == 0) red[threadIdx.x >> 5] = s;
    __syncthreads();
    if (threadIdx.x == 0) {
        float v = 0.f;
        #pragma unroll
        for (int i = 0; i < 8; i++) v += red[i];
        out[b] = v + fc_b[0];
    }
}

// ---------------------------------------------------------------------------
extern "C" void kernel_launch(void* const* d_in, const int* in_sizes, int n_in,
                              void* d_out, int out_size)
{
    (void)in_sizes; (void)n_in; (void)out_size;
    const float* x      = (const float*)d_in[0];
    const float* w_ih0  = (const float*)d_in[1];
    const float* w_rest = (const float*)d_in[2];
    const float* w_hh   = (const float*)d_in[3];
    const float* b_ih   = (const float*)d_in[4];
    const float* b_hh   = (const float*)d_in[5];
    const float* fc_w   = (const float*)d_in[6];
    const float* fc_b   = (const float*)d_in[7];
    float* out = (float*)d_out;

    const int lstm_smem = (32 * SWP + 2 * 64 * 132) * 4 + (64 * 32 + 64 * 33 + 512) * 4; // 217,856 B
    const int proj_smem = (2 * 128 * 36 + 2 * 64 * 36) * 4;                               // 55,296 B
    static bool attr_set = false;
    if (!attr_set) {
        cudaFuncSetAttribute(lstm_layer_kernel,
                             cudaFuncAttributeMaxDynamicSharedMemorySize, lstm_smem);
        cudaFuncSetAttribute(proj_kernel,
                             cudaFuncAttributeMaxDynamicSharedMemorySize, proj_smem);
        attr_set = true;
    }

    reset_kernel<<<1, 1>>>();

    layer0_xp_kernel<<<(TSTEPS * BATCH * GDIM) / 256, 256>>>(x, w_ih0, b_ih, b_hh);

    for (int l = 0; l < NLAYERS; l++) {
        if (l > 0) {
            proj_kernel<<<dim3(64, 128), 256, proj_smem>>>(
                w_rest + (size_t)(l - 1) * GDIM * HDIM,
                b_ih + (size_t)l * GDIM,
                b_hh + (size_t)l * GDIM);
        }
        lstm_layer_kernel<<<128, 256, lstm_smem>>>(
            w_hh + (size_t)l * GDIM * HDIM, l * TSTEPS);
    }

    fc_kernel<<<BATCH, 256>>>(fc_w, fc_b, out);
}